// round 6
// baseline (speedup 1.0000x reference)
#include <cuda_runtime.h>
#include <cstdio>

#define NB    8
#define CIN   256
#define CI    128
#define NPIX  2304          // 48*48
#define BN    64            // n/m tile
#define NT    (NPIX/BN)     // 36 tiles

// ---------------- f32x2 packed math helpers ----------------
__device__ __forceinline__ unsigned long long pack2(float lo, float hi) {
    unsigned long long d;
    asm("mov.b64 %0, {%1, %2};"
        : "=l"(d) : "r"(__float_as_uint(lo)), "r"(__float_as_uint(hi)));
    return d;
}
__device__ __forceinline__ unsigned long long fma2(unsigned long long a,
                                                   unsigned long long b,
                                                   unsigned long long c) {
    unsigned long long d;
    asm("fma.rn.f32x2 %0, %1, %2, %3;" : "=l"(d) : "l"(a), "l"(b), "l"(c));
    return d;
}
__device__ __forceinline__ float2 unpack2(unsigned long long v) {
    unsigned int lo, hi;
    asm("mov.b64 {%0, %1}, %2;" : "=r"(lo), "=r"(hi) : "l"(v));
    return make_float2(__uint_as_float(lo), __uint_as_float(hi));
}

// ---------------- scratch (no allocations allowed) ----------------
__device__ float g_Q1[NB][CI][NPIX];
__device__ float g_K1[NB][CI][NPIX];
__device__ float g_V1t[NB][NPIX][CI];   // transposed: [n][c]
__device__ float g_Q2[NB][CI][NPIX];
__device__ float g_K2[NB][CI][NPIX];
__device__ float g_V2t[NB][NPIX][CI];
__device__ float g_wT[6][CIN][CI];      // transposed weights [c][o]

// ---------------- weight transpose ----------------
__global__ void wtrans_kernel(const float* __restrict__ w0, const float* __restrict__ w1,
                              const float* __restrict__ w2, const float* __restrict__ w3,
                              const float* __restrict__ w4, const float* __restrict__ w5)
{
    int conv = blockIdx.x;
    const float* w;
    switch (conv) {
        case 0: w = w0; break; case 1: w = w1; break; case 2: w = w2; break;
        case 3: w = w3; break; case 4: w = w4; break; default: w = w5; break;
    }
    for (int idx = threadIdx.x; idx < CI * CIN; idx += blockDim.x) {
        int o = idx / CIN;
        int c = idx % CIN;          // consecutive threads -> consecutive c -> coalesced read
        g_wT[conv][c][o] = w[o * CIN + c];
    }
}

// ---------------- 1x1 conv: out[o][n] = sum_c wT[c][o]*x[c][n] + bias[o] ----------------
// grid: (36 ntiles, 8 batch, 6 convs), block 256 (16x16), micro-tile 8o x 4n (f32x2 over o)
__global__ __launch_bounds__(256) void conv_kernel(
    const float* __restrict__ x1, const float* __restrict__ x2,
    const float* __restrict__ bv1, const float* __restrict__ bk1, const float* __restrict__ bq1,
    const float* __restrict__ bv2, const float* __restrict__ bk2, const float* __restrict__ bq2)
{
    const int conv = blockIdx.z;
    const int b    = blockIdx.y;
    const int gn0  = blockIdx.x * BN;

    const float* x = (conv < 3) ? x1 : x2;
    const float* bias;
    float* outp;
    bool trans = false;
    switch (conv) {
        case 0: bias = bv1; outp = &g_V1t[0][0][0]; trans = true;  break;
        case 1: bias = bk1; outp = &g_K1[0][0][0];                 break;
        case 2: bias = bq1; outp = &g_Q1[0][0][0];                 break;
        case 3: bias = bv2; outp = &g_V2t[0][0][0]; trans = true;  break;
        case 4: bias = bk2; outp = &g_K2[0][0][0];                 break;
        default: bias = bq2; outp = &g_Q2[0][0][0];                break;
    }

    __shared__ float Ws[32][CI + 4];   // [k][o], stride 132
    __shared__ float Xs[32][BN + 4];   // [k][n], stride 68

    const int t  = threadIdx.x;
    const int tx = t & 15;
    const int ty = t >> 4;
    const int o0  = tx * 8;
    const int n0l = ty * 4;

    // packed accumulators: acc2[p][j] holds channels (o0+2p, o0+2p+1), n = n0l+j
    unsigned long long acc2[4][4];
    #pragma unroll
    for (int p = 0; p < 4; p++) {
        unsigned long long bp = pack2(bias[o0 + 2 * p], bias[o0 + 2 * p + 1]);
        #pragma unroll
        for (int j = 0; j < 4; j++) acc2[p][j] = bp;
    }

    const float* xb = x + (size_t)b * CIN * NPIX + gn0;
    const float* wt = &g_wT[conv][0][0];

    for (int c0 = 0; c0 < CIN; c0 += 32) {
        // stage weights: 32x128 = 1024 float4
        #pragma unroll
        for (int i = 0; i < 4; i++) {
            int idx4 = t + i * 256;
            int k = idx4 >> 5, o4 = idx4 & 31;
            *(float4*)&Ws[k][o4 * 4] = *(const float4*)&wt[(size_t)(c0 + k) * CI + o4 * 4];
        }
        // stage x: 32x64 = 512 float4
        #pragma unroll
        for (int i = 0; i < 2; i++) {
            int idx4 = t + i * 256;
            int k = idx4 >> 4, n4 = idx4 & 15;
            *(float4*)&Xs[k][n4 * 4] = *(const float4*)&xb[(size_t)(c0 + k) * NPIX + n4 * 4];
        }
        __syncthreads();
        #pragma unroll
        for (int k = 0; k < 32; k++) {
            float4 w0 = *(float4*)&Ws[k][o0];
            float4 w1 = *(float4*)&Ws[k][o0 + 4];
            float4 xv = *(float4*)&Xs[k][n0l];
            unsigned long long wp[4];
            wp[0] = pack2(w0.x, w0.y);  wp[1] = pack2(w0.z, w0.w);
            wp[2] = pack2(w1.x, w1.y);  wp[3] = pack2(w1.z, w1.w);
            float xr[4] = {xv.x, xv.y, xv.z, xv.w};
            #pragma unroll
            for (int j = 0; j < 4; j++) {
                unsigned long long xbcast = pack2(xr[j], xr[j]);
                #pragma unroll
                for (int p = 0; p < 4; p++)
                    acc2[p][j] = fma2(wp[p], xbcast, acc2[p][j]);
            }
        }
        __syncthreads();
    }

    // unpack
    float acc[8][4];
    #pragma unroll
    for (int p = 0; p < 4; p++)
        #pragma unroll
        for (int j = 0; j < 4; j++) {
            float2 v = unpack2(acc2[p][j]);
            acc[2 * p][j]     = v.x;
            acc[2 * p + 1][j] = v.y;
        }

    if (trans) {
        float* vp = outp + (size_t)b * NPIX * CI;
        #pragma unroll
        for (int j = 0; j < 4; j++) {
            size_t gn = gn0 + n0l + j;
            float4 v0 = make_float4(acc[0][j], acc[1][j], acc[2][j], acc[3][j]);
            float4 v1 = make_float4(acc[4][j], acc[5][j], acc[6][j], acc[7][j]);
            *(float4*)&vp[gn * CI + o0]     = v0;
            *(float4*)&vp[gn * CI + o0 + 4] = v1;
        }
    } else {
        float* op = outp + (size_t)b * CI * NPIX + gn0;
        #pragma unroll
        for (int i = 0; i < 8; i++) {
            float4 v = make_float4(acc[i][0], acc[i][1], acc[i][2], acc[i][3]);
            *(float4*)&op[(size_t)(o0 + i) * NPIX + n0l] = v;
        }
    }
}

// ---------------- copy x into first 256 channels of y ----------------
__global__ void copyx_kernel(const float* __restrict__ x1, const float* __restrict__ x2,
                             float* __restrict__ out)
{
    const size_t per = (size_t)NB * CIN * NPIX / 4;   // float4 count per input
    size_t idx4 = (size_t)blockIdx.x * blockDim.x + threadIdx.x;
    if (idx4 >= 2 * per) return;
    int which = idx4 >= per;
    size_t r  = idx4 - (size_t)which * per;
    size_t bb = r / ((size_t)CIN * NPIX / 4);
    size_t cn = r % ((size_t)CIN * NPIX / 4);
    const float4* src = (const float4*)(which ? x2 : x1);
    float4* dst = (float4*)out + (size_t)which * NB * 384 * NPIX / 4
                               + bb * (384 * NPIX / 4) + cn;
    *dst = src[r];
}

// ---------------- fused sigmoid-gated cross attention ----------------
// Fu[c][n] = sum_m sigmoid( sum_k Q[k][n]*K[k][m] ) * V[c][m]
// grid: (36 ntiles, 8 batch, 2 dir), block 256 (16x16)
// smem floats: Q 128*68 + K 128*68 + Vt 64*132 + S 64*68 = 30208 (120832 B)
#define ATTN_SMEM_FLOATS (128*68 + 128*68 + 64*132 + 64*68)

__global__ __launch_bounds__(256) void attn_kernel(float* __restrict__ out)
{
    extern __shared__ float sm[];
    float* Qs = sm;                         // [128][68]
    float* Ks = sm + 128 * 68;              // [128][68]
    float* Vs = sm + 2 * 128 * 68;          // [64][132]  ([m][c])
    float* Ss = Vs + 64 * 132;              // [64][68]   ([n][m])

    const int gn0 = blockIdx.x * BN;
    const int b   = blockIdx.y;
    const int dir = blockIdx.z;

    const float* Qg = dir == 0 ? &g_Q1[b][0][0]  : &g_Q2[b][0][0];
    const float* Kg = dir == 0 ? &g_K2[b][0][0]  : &g_K1[b][0][0];
    const float* Vg = dir == 0 ? &g_V2t[b][0][0] : &g_V1t[b][0][0];

    const int t  = threadIdx.x;
    const int tx = t & 15;
    const int ty = t >> 4;
    const int c0  = tx * 8;    // Fu micro-tile: 8 channels
    const int n0l = ty * 4;    // 4 n

    // stage Q tile once: 128x64
    #pragma unroll
    for (int i = 0; i < 8; i++) {
        int idx4 = t + i * 256;
        int k = idx4 >> 4, n4 = idx4 & 15;
        *(float4*)&Qs[k * 68 + n4 * 4] = *(const float4*)&Qg[(size_t)k * NPIX + gn0 + n4 * 4];
    }

    // Fu accumulators packed over channel pairs: acc2[p][j] = (c0+2p, c0+2p+1) x (n0l+j)
    unsigned long long acc2[4][4];
    #pragma unroll
    for (int p = 0; p < 4; p++)
        #pragma unroll
        for (int j = 0; j < 4; j++) acc2[p][j] = 0ull;

    for (int gm0 = 0; gm0 < NPIX; gm0 += BN) {
        // stage K tile 128x64 and V tile 64x128
        #pragma unroll
        for (int i = 0; i < 8; i++) {
            int idx4 = t + i * 256;
            int k = idx4 >> 4, n4 = idx4 & 15;
            *(float4*)&Ks[k * 68 + n4 * 4] = *(const float4*)&Kg[(size_t)k * NPIX + gm0 + n4 * 4];
        }
        #pragma unroll
        for (int i = 0; i < 8; i++) {
            int idx4 = t + i * 256;
            int r = idx4 >> 5, c4 = idx4 & 31;
            *(float4*)&Vs[r * 132 + c4 * 4] = *(const float4*)&Vg[(size_t)(gm0 + r) * CI + c4 * 4];
        }
        __syncthreads();

        // S[n][m] micro 4x4: n from ty, m from tx (scalar FFMA; LDS/FMA balanced here)
        float sacc[4][4];
        #pragma unroll
        for (int j = 0; j < 4; j++)
            #pragma unroll
            for (int i = 0; i < 4; i++) sacc[j][i] = 0.f;

        #pragma unroll 8
        for (int k = 0; k < CI; k++) {
            float4 qv = *(float4*)&Qs[k * 68 + n0l];
            float4 kv = *(float4*)&Ks[k * 68 + tx * 4];
            float qr[4] = {qv.x, qv.y, qv.z, qv.w};
            float kr[4] = {kv.x, kv.y, kv.z, kv.w};
            #pragma unroll
            for (int j = 0; j < 4; j++)
                #pragma unroll
                for (int i = 0; i < 4; i++)
                    sacc[j][i] += qr[j] * kr[i];
        }
        // sigmoid + stage to smem
        #pragma unroll
        for (int j = 0; j < 4; j++) {
            float4 sv;
            sv.x = 1.f / (1.f + __expf(-sacc[j][0]));
            sv.y = 1.f / (1.f + __expf(-sacc[j][1]));
            sv.z = 1.f / (1.f + __expf(-sacc[j][2]));
            sv.w = 1.f / (1.f + __expf(-sacc[j][3]));
            *(float4*)&Ss[(n0l + j) * 68 + tx * 4] = sv;
        }
        __syncthreads();

        // Fu accumulate (f32x2): acc2[p][j] += Vpair[m][2p..] * S[n0l+j][m]
        #pragma unroll 1
        for (int m4 = 0; m4 < 16; m4++) {
            int m = m4 * 4;
            float4 s0 = *(float4*)&Ss[(n0l + 0) * 68 + m];
            float4 s1 = *(float4*)&Ss[(n0l + 1) * 68 + m];
            float4 s2 = *(float4*)&Ss[(n0l + 2) * 68 + m];
            float4 s3 = *(float4*)&Ss[(n0l + 3) * 68 + m];
            float sr[4][4] = {{s0.x, s0.y, s0.z, s0.w},
                              {s1.x, s1.y, s1.z, s1.w},
                              {s2.x, s2.y, s2.z, s2.w},
                              {s3.x, s3.y, s3.z, s3.w}};
            #pragma unroll
            for (int mm = 0; mm < 4; mm++) {
                float4 v0 = *(float4*)&Vs[(m + mm) * 132 + c0];
                float4 v1 = *(float4*)&Vs[(m + mm) * 132 + c0 + 4];
                unsigned long long vp[4];
                vp[0] = pack2(v0.x, v0.y);  vp[1] = pack2(v0.z, v0.w);
                vp[2] = pack2(v1.x, v1.y);  vp[3] = pack2(v1.z, v1.w);
                #pragma unroll
                for (int j = 0; j < 4; j++) {
                    unsigned long long sb = pack2(sr[j][mm], sr[j][mm]);
                    #pragma unroll
                    for (int p = 0; p < 4; p++)
                        acc2[p][j] = fma2(vp[p], sb, acc2[p][j]);
                }
            }
        }
        __syncthreads();
    }

    // unpack + write Fu into channels [256,384) of y
    float acc[8][4];
    #pragma unroll
    for (int p = 0; p < 4; p++)
        #pragma unroll
        for (int j = 0; j < 4; j++) {
            float2 v = unpack2(acc2[p][j]);
            acc[2 * p][j]     = v.x;
            acc[2 * p + 1][j] = v.y;
        }

    float* ob = out + (size_t)dir * NB * 384 * NPIX
                    + (size_t)b * 384 * NPIX + (size_t)256 * NPIX + gn0;
    #pragma unroll
    for (int i = 0; i < 8; i++) {
        float4 v = make_float4(acc[i][0], acc[i][1], acc[i][2], acc[i][3]);
        *(float4*)&ob[(size_t)(c0 + i) * NPIX + n0l] = v;
    }
}

// ---------------- launch ----------------
extern "C" void kernel_launch(void* const* d_in, const int* in_sizes, int n_in,
                              void* d_out, int out_size)
{
    const float* x1  = (const float*)d_in[0];
    const float* x2  = (const float*)d_in[1];
    const float* wv1 = (const float*)d_in[2];  const float* bv1 = (const float*)d_in[3];
    const float* wk1 = (const float*)d_in[4];  const float* bk1 = (const float*)d_in[5];
    const float* wq1 = (const float*)d_in[6];  const float* bq1 = (const float*)d_in[7];
    const float* wv2 = (const float*)d_in[8];  const float* bv2 = (const float*)d_in[9];
    const float* wk2 = (const float*)d_in[10]; const float* bk2 = (const float*)d_in[11];
    const float* wq2 = (const float*)d_in[12]; const float* bq2 = (const float*)d_in[13];
    float* out = (float*)d_out;

    // weights: transposed copies for coalesced conv staging
    wtrans_kernel<<<6, 256>>>(wv1, wk1, wq1, wv2, wk2, wq2);

    // 6 fused 1x1 convs (V written pre-transposed)
    dim3 cg(NT, NB, 6);
    conv_kernel<<<cg, 256>>>(x1, x2, bv1, bk1, bq1, bv2, bk2, bq2);

    // pass-through channels of y
    {
        size_t tot4 = 2ull * NB * CIN * NPIX / 4;
        int blocks = (int)((tot4 + 255) / 256);
        copyx_kernel<<<blocks, 256>>>(x1, x2, out);
    }

    // fused attention
    size_t smem_bytes = (size_t)ATTN_SMEM_FLOATS * sizeof(float);
    cudaFuncSetAttribute(attn_kernel, cudaFuncAttributeMaxDynamicSharedMemorySize,
                         (int)smem_bytes);
    dim3 ag(NT, NB, 2);
    attn_kernel<<<ag, 256, smem_bytes>>>(out);
}

// round 7
// speedup vs baseline: 1.3698x; 1.3698x over previous
#include <cuda_runtime.h>
#include <cstdio>

#define NB    8
#define CIN   256
#define CI    128
#define NPIX  2304          // 48*48
#define BN    64            // n/m tile
#define NT    (NPIX/BN)     // 36 tiles

// ---------------- f32x2 packed math helpers ----------------
__device__ __forceinline__ unsigned long long pack2(float lo, float hi) {
    unsigned long long d;
    asm("mov.b64 %0, {%1, %2};"
        : "=l"(d) : "r"(__float_as_uint(lo)), "r"(__float_as_uint(hi)));
    return d;
}
__device__ __forceinline__ unsigned long long fma2(unsigned long long a,
                                                   unsigned long long b,
                                                   unsigned long long c) {
    unsigned long long d;
    asm("fma.rn.f32x2 %0, %1, %2, %3;" : "=l"(d) : "l"(a), "l"(b), "l"(c));
    return d;
}
__device__ __forceinline__ float2 unpack2(unsigned long long v) {
    unsigned int lo, hi;
    asm("mov.b64 {%0, %1}, %2;" : "=r"(lo), "=r"(hi) : "l"(v));
    return make_float2(__uint_as_float(lo), __uint_as_float(hi));
}

// ---------------- scratch (no allocations allowed) ----------------
__device__ float g_Q1[NB][CI][NPIX];
__device__ float g_K1[NB][CI][NPIX];
__device__ float g_V1t[NB][NPIX][CI];   // transposed: [n][c]
__device__ float g_Q2[NB][CI][NPIX];
__device__ float g_K2[NB][CI][NPIX];
__device__ float g_V2t[NB][NPIX][CI];
__device__ float g_wT[6][CIN][CI];      // transposed weights [c][o]

// ---------------- weight transpose ----------------
__global__ void wtrans_kernel(const float* __restrict__ w0, const float* __restrict__ w1,
                              const float* __restrict__ w2, const float* __restrict__ w3,
                              const float* __restrict__ w4, const float* __restrict__ w5)
{
    int conv = blockIdx.x;
    const float* w;
    switch (conv) {
        case 0: w = w0; break; case 1: w = w1; break; case 2: w = w2; break;
        case 3: w = w3; break; case 4: w = w4; break; default: w = w5; break;
    }
    for (int idx = threadIdx.x; idx < CI * CIN; idx += blockDim.x) {
        int o = idx / CIN;
        int c = idx % CIN;          // consecutive threads -> consecutive c -> coalesced read
        g_wT[conv][c][o] = w[o * CIN + c];
    }
}

// ---------------- 1x1 conv: out[o][n] = sum_c wT[c][o]*x[c][n] + bias[o] ----------------
// grid: (36 ntiles, 8 batch, 6 convs), block 256 (16x16), micro-tile 8o x 4n (f32x2 over o)
__global__ __launch_bounds__(256) void conv_kernel(
    const float* __restrict__ x1, const float* __restrict__ x2,
    const float* __restrict__ bv1, const float* __restrict__ bk1, const float* __restrict__ bq1,
    const float* __restrict__ bv2, const float* __restrict__ bk2, const float* __restrict__ bq2)
{
    const int conv = blockIdx.z;
    const int b    = blockIdx.y;
    const int gn0  = blockIdx.x * BN;

    const float* x = (conv < 3) ? x1 : x2;
    const float* bias;
    float* outp;
    bool trans = false;
    switch (conv) {
        case 0: bias = bv1; outp = &g_V1t[0][0][0]; trans = true;  break;
        case 1: bias = bk1; outp = &g_K1[0][0][0];                 break;
        case 2: bias = bq1; outp = &g_Q1[0][0][0];                 break;
        case 3: bias = bv2; outp = &g_V2t[0][0][0]; trans = true;  break;
        case 4: bias = bk2; outp = &g_K2[0][0][0];                 break;
        default: bias = bq2; outp = &g_Q2[0][0][0];                break;
    }

    __shared__ float Ws[32][CI + 4];   // [k][o], stride 132
    __shared__ float Xs[32][BN + 4];   // [k][n], stride 68

    const int t  = threadIdx.x;
    const int tx = t & 15;
    const int ty = t >> 4;
    const int o0  = tx * 8;
    const int n0l = ty * 4;

    // packed accumulators: acc2[p][j] holds channels (o0+2p, o0+2p+1), n = n0l+j
    unsigned long long acc2[4][4];
    #pragma unroll
    for (int p = 0; p < 4; p++) {
        unsigned long long bp = pack2(bias[o0 + 2 * p], bias[o0 + 2 * p + 1]);
        #pragma unroll
        for (int j = 0; j < 4; j++) acc2[p][j] = bp;
    }

    const float* xb = x + (size_t)b * CIN * NPIX + gn0;
    const float* wt = &g_wT[conv][0][0];

    for (int c0 = 0; c0 < CIN; c0 += 32) {
        // stage weights: 32x128 = 1024 float4
        #pragma unroll
        for (int i = 0; i < 4; i++) {
            int idx4 = t + i * 256;
            int k = idx4 >> 5, o4 = idx4 & 31;
            *(float4*)&Ws[k][o4 * 4] = *(const float4*)&wt[(size_t)(c0 + k) * CI + o4 * 4];
        }
        // stage x: 32x64 = 512 float4
        #pragma unroll
        for (int i = 0; i < 2; i++) {
            int idx4 = t + i * 256;
            int k = idx4 >> 4, n4 = idx4 & 15;
            *(float4*)&Xs[k][n4 * 4] = *(const float4*)&xb[(size_t)(c0 + k) * NPIX + n4 * 4];
        }
        __syncthreads();
        #pragma unroll
        for (int k = 0; k < 32; k++) {
            float4 w0 = *(float4*)&Ws[k][o0];
            float4 w1 = *(float4*)&Ws[k][o0 + 4];
            float4 xv = *(float4*)&Xs[k][n0l];
            unsigned long long wp[4];
            wp[0] = pack2(w0.x, w0.y);  wp[1] = pack2(w0.z, w0.w);
            wp[2] = pack2(w1.x, w1.y);  wp[3] = pack2(w1.z, w1.w);
            float xr[4] = {xv.x, xv.y, xv.z, xv.w};
            #pragma unroll
            for (int j = 0; j < 4; j++) {
                unsigned long long xbcast = pack2(xr[j], xr[j]);
                #pragma unroll
                for (int p = 0; p < 4; p++)
                    acc2[p][j] = fma2(wp[p], xbcast, acc2[p][j]);
            }
        }
        __syncthreads();
    }

    // unpack
    float acc[8][4];
    #pragma unroll
    for (int p = 0; p < 4; p++)
        #pragma unroll
        for (int j = 0; j < 4; j++) {
            float2 v = unpack2(acc2[p][j]);
            acc[2 * p][j]     = v.x;
            acc[2 * p + 1][j] = v.y;
        }

    if (trans) {
        float* vp = outp + (size_t)b * NPIX * CI;
        #pragma unroll
        for (int j = 0; j < 4; j++) {
            size_t gn = gn0 + n0l + j;
            float4 v0 = make_float4(acc[0][j], acc[1][j], acc[2][j], acc[3][j]);
            float4 v1 = make_float4(acc[4][j], acc[5][j], acc[6][j], acc[7][j]);
            *(float4*)&vp[gn * CI + o0]     = v0;
            *(float4*)&vp[gn * CI + o0 + 4] = v1;
        }
    } else {
        float* op = outp + (size_t)b * CI * NPIX + gn0;
        #pragma unroll
        for (int i = 0; i < 8; i++) {
            float4 v = make_float4(acc[i][0], acc[i][1], acc[i][2], acc[i][3]);
            *(float4*)&op[(size_t)(o0 + i) * NPIX + n0l] = v;
        }
    }
}

// ---------------- copy x into first 256 channels of y ----------------
__global__ void copyx_kernel(const float* __restrict__ x1, const float* __restrict__ x2,
                             float* __restrict__ out)
{
    const size_t per = (size_t)NB * CIN * NPIX / 4;   // float4 count per input
    size_t idx4 = (size_t)blockIdx.x * blockDim.x + threadIdx.x;
    if (idx4 >= 2 * per) return;
    int which = idx4 >= per;
    size_t r  = idx4 - (size_t)which * per;
    size_t bb = r / ((size_t)CIN * NPIX / 4);
    size_t cn = r % ((size_t)CIN * NPIX / 4);
    const float4* src = (const float4*)(which ? x2 : x1);
    float4* dst = (float4*)out + (size_t)which * NB * 384 * NPIX / 4
                               + bb * (384 * NPIX / 4) + cn;
    *dst = src[r];
}

// ---------------- fused sigmoid-gated cross attention ----------------
// Fu[c][n] = sum_m sigmoid( sum_k Q[k][n]*K[k][m] ) * V[c][m]
// grid: (36 ntiles, 8 batch, 2 dir), block 256 (16x16), 2 CTAs/SM
// smem: Q 128*68 + K 128*68 (S 64*68 ALIASES K) + Vt 64*132
//     = 25856 floats = 103424 B  -> two CTAs fit in 228KB
#define ATTN_SMEM_FLOATS (2*128*68 + 64*132)

__global__ __launch_bounds__(256, 2) void attn_kernel(float* __restrict__ out)
{
    extern __shared__ float sm[];
    float* Qs = sm;                         // [128][68]
    float* Ks = sm + 128 * 68;              // [128][68]
    float* Ss = Ks;                         // [64][68]  (aliases Ks; ordered by barriers)
    float* Vs = sm + 2 * 128 * 68;          // [64][132] ([m][c])

    const int gn0 = blockIdx.x * BN;
    const int b   = blockIdx.y;
    const int dir = blockIdx.z;

    const float* Qg = dir == 0 ? &g_Q1[b][0][0]  : &g_Q2[b][0][0];
    const float* Kg = dir == 0 ? &g_K2[b][0][0]  : &g_K1[b][0][0];
    const float* Vg = dir == 0 ? &g_V2t[b][0][0] : &g_V1t[b][0][0];

    const int t  = threadIdx.x;
    const int tx = t & 15;
    const int ty = t >> 4;
    const int c0  = tx * 8;    // Fu micro-tile: 8 channels
    const int n0l = ty * 4;    // 4 n

    // stage Q tile once: 128x64 (first loop-top barrier publishes it)
    #pragma unroll
    for (int i = 0; i < 8; i++) {
        int idx4 = t + i * 256;
        int k = idx4 >> 4, n4 = idx4 & 15;
        *(float4*)&Qs[k * 68 + n4 * 4] = *(const float4*)&Qg[(size_t)k * NPIX + gn0 + n4 * 4];
    }

    // Fu accumulators packed over channel pairs: acc2[p][j] = (c0+2p, c0+2p+1) x (n0l+j)
    unsigned long long acc2[4][4];
    #pragma unroll
    for (int p = 0; p < 4; p++)
        #pragma unroll
        for (int j = 0; j < 4; j++) acc2[p][j] = 0ull;

    for (int gm0 = 0; gm0 < NPIX; gm0 += BN) {
        __syncthreads();   // prev PV done reading Ss(/Ks) & Vs; Qs published on 1st iter

        // stage K tile 128x64 and V tile 64x128
        #pragma unroll
        for (int i = 0; i < 8; i++) {
            int idx4 = t + i * 256;
            int k = idx4 >> 4, n4 = idx4 & 15;
            *(float4*)&Ks[k * 68 + n4 * 4] = *(const float4*)&Kg[(size_t)k * NPIX + gm0 + n4 * 4];
        }
        #pragma unroll
        for (int i = 0; i < 8; i++) {
            int idx4 = t + i * 256;
            int r = idx4 >> 5, c4 = idx4 & 31;
            *(float4*)&Vs[r * 132 + c4 * 4] = *(const float4*)&Vg[(size_t)(gm0 + r) * CI + c4 * 4];
        }
        __syncthreads();

        // S[n][m] micro 4x4 (f32x2 over m pairs): n from ty, m from tx
        unsigned long long sacc2[4][2];
        #pragma unroll
        for (int j = 0; j < 4; j++) {
            sacc2[j][0] = 0ull; sacc2[j][1] = 0ull;
        }

        #pragma unroll 8
        for (int k = 0; k < CI; k++) {
            float4 qv = *(float4*)&Qs[k * 68 + n0l];
            float4 kv = *(float4*)&Ks[k * 68 + tx * 4];
            unsigned long long kp0 = pack2(kv.x, kv.y);
            unsigned long long kp1 = pack2(kv.z, kv.w);
            float qr[4] = {qv.x, qv.y, qv.z, qv.w};
            #pragma unroll
            for (int j = 0; j < 4; j++) {
                unsigned long long qb = pack2(qr[j], qr[j]);
                sacc2[j][0] = fma2(qb, kp0, sacc2[j][0]);
                sacc2[j][1] = fma2(qb, kp1, sacc2[j][1]);
            }
        }
        __syncthreads();   // QK done reading Ks -> safe to overwrite with Ss

        // sigmoid + stage to smem (Ss aliases Ks)
        #pragma unroll
        for (int j = 0; j < 4; j++) {
            float2 a = unpack2(sacc2[j][0]);
            float2 c = unpack2(sacc2[j][1]);
            float4 sv;
            sv.x = 1.f / (1.f + __expf(-a.x));
            sv.y = 1.f / (1.f + __expf(-a.y));
            sv.z = 1.f / (1.f + __expf(-c.x));
            sv.w = 1.f / (1.f + __expf(-c.y));
            *(float4*)&Ss[(n0l + j) * 68 + tx * 4] = sv;
        }
        __syncthreads();

        // Fu accumulate (f32x2): acc2[p][j] += Vpair[m][2p..] * S[n0l+j][m]
        #pragma unroll 2
        for (int m4 = 0; m4 < 16; m4++) {
            int m = m4 * 4;
            float4 s0 = *(float4*)&Ss[(n0l + 0) * 68 + m];
            float4 s1 = *(float4*)&Ss[(n0l + 1) * 68 + m];
            float4 s2 = *(float4*)&Ss[(n0l + 2) * 68 + m];
            float4 s3 = *(float4*)&Ss[(n0l + 3) * 68 + m];
            float sr[4][4] = {{s0.x, s0.y, s0.z, s0.w},
                              {s1.x, s1.y, s1.z, s1.w},
                              {s2.x, s2.y, s2.z, s2.w},
                              {s3.x, s3.y, s3.z, s3.w}};
            #pragma unroll
            for (int mm = 0; mm < 4; mm++) {
                float4 v0 = *(float4*)&Vs[(m + mm) * 132 + c0];
                float4 v1 = *(float4*)&Vs[(m + mm) * 132 + c0 + 4];
                unsigned long long vp[4];
                vp[0] = pack2(v0.x, v0.y);  vp[1] = pack2(v0.z, v0.w);
                vp[2] = pack2(v1.x, v1.y);  vp[3] = pack2(v1.z, v1.w);
                #pragma unroll
                for (int j = 0; j < 4; j++) {
                    unsigned long long sb = pack2(sr[j][mm], sr[j][mm]);
                    #pragma unroll
                    for (int p = 0; p < 4; p++)
                        acc2[p][j] = fma2(vp[p], sb, acc2[p][j]);
                }
            }
        }
    }

    // unpack + write Fu into channels [256,384) of y
    float acc[8][4];
    #pragma unroll
    for (int p = 0; p < 4; p++)
        #pragma unroll
        for (int j = 0; j < 4; j++) {
            float2 v = unpack2(acc2[p][j]);
            acc[2 * p][j]     = v.x;
            acc[2 * p + 1][j] = v.y;
        }

    float* ob = out + (size_t)dir * NB * 384 * NPIX
                    + (size_t)b * 384 * NPIX + (size_t)256 * NPIX + gn0;
    #pragma unroll
    for (int i = 0; i < 8; i++) {
        float4 v = make_float4(acc[i][0], acc[i][1], acc[i][2], acc[i][3]);
        *(float4*)&ob[(size_t)(c0 + i) * NPIX + n0l] = v;
    }
}

// ---------------- launch ----------------
extern "C" void kernel_launch(void* const* d_in, const int* in_sizes, int n_in,
                              void* d_out, int out_size)
{
    const float* x1  = (const float*)d_in[0];
    const float* x2  = (const float*)d_in[1];
    const float* wv1 = (const float*)d_in[2];  const float* bv1 = (const float*)d_in[3];
    const float* wk1 = (const float*)d_in[4];  const float* bk1 = (const float*)d_in[5];
    const float* wq1 = (const float*)d_in[6];  const float* bq1 = (const float*)d_in[7];
    const float* wv2 = (const float*)d_in[8];  const float* bv2 = (const float*)d_in[9];
    const float* wk2 = (const float*)d_in[10]; const float* bk2 = (const float*)d_in[11];
    const float* wq2 = (const float*)d_in[12]; const float* bq2 = (const float*)d_in[13];
    float* out = (float*)d_out;

    // weights: transposed copies for coalesced conv staging
    wtrans_kernel<<<6, 256>>>(wv1, wk1, wq1, wv2, wk2, wq2);

    // 6 fused 1x1 convs (V written pre-transposed)
    dim3 cg(NT, NB, 6);
    conv_kernel<<<cg, 256>>>(x1, x2, bv1, bk1, bq1, bv2, bk2, bq2);

    // pass-through channels of y
    {
        size_t tot4 = 2ull * NB * CIN * NPIX / 4;
        int blocks = (int)((tot4 + 255) / 256);
        copyx_kernel<<<blocks, 256>>>(x1, x2, out);
    }

    // fused attention (2 CTAs/SM)
    size_t smem_bytes = (size_t)ATTN_SMEM_FLOATS * sizeof(float);
    cudaFuncSetAttribute(attn_kernel, cudaFuncAttributeMaxDynamicSharedMemorySize,
                         (int)smem_bytes);
    dim3 ag(NT, NB, 2);
    attn_kernel<<<ag, 256, smem_bytes>>>(out);
}

// round 9
// speedup vs baseline: 1.5377x; 1.1225x over previous
#include <cuda_runtime.h>

#define NB    8
#define CIN   256
#define CI    128
#define NPIX  2304          // 48*48
#define BN    64            // conv n tile
#define NT    (NPIX/BN)     // 36
#define TQ    128           // attn n/m tile
#define NTA   (NPIX/TQ)     // 18

// ---------------- f32x2 packed math helpers ----------------
__device__ __forceinline__ unsigned long long pack2(float lo, float hi) {
    unsigned long long d;
    asm("mov.b64 %0, {%1, %2};"
        : "=l"(d) : "r"(__float_as_uint(lo)), "r"(__float_as_uint(hi)));
    return d;
}
__device__ __forceinline__ unsigned long long fma2(unsigned long long a,
                                                   unsigned long long b,
                                                   unsigned long long c) {
    unsigned long long d;
    asm("fma.rn.f32x2 %0, %1, %2, %3;" : "=l"(d) : "l"(a), "l"(b), "l"(c));
    return d;
}
__device__ __forceinline__ float2 unpack2(unsigned long long v) {
    unsigned int lo, hi;
    asm("mov.b64 {%0, %1}, %2;" : "=r"(lo), "=r"(hi) : "l"(v));
    return make_float2(__uint_as_float(lo), __uint_as_float(hi));
}
__device__ __forceinline__ float f4get(const float4& v, int i) {
    return i == 0 ? v.x : (i == 1 ? v.y : (i == 2 ? v.z : v.w));
}

// ---------------- scratch ----------------
__device__ float g_Q1[NB][CI][NPIX];
__device__ float g_K1[NB][CI][NPIX];
__device__ float g_V1t[NB][NPIX][CI];   // [n][c]
__device__ float g_Q2[NB][CI][NPIX];
__device__ float g_K2[NB][CI][NPIX];
__device__ float g_V2t[NB][NPIX][CI];
__device__ float g_wT[6][CIN][CI];      // [c][o]

// ---------------- weight transpose ----------------
__global__ void wtrans_kernel(const float* __restrict__ w0, const float* __restrict__ w1,
                              const float* __restrict__ w2, const float* __restrict__ w3,
                              const float* __restrict__ w4, const float* __restrict__ w5)
{
    int conv = blockIdx.x;
    const float* w;
    switch (conv) {
        case 0: w = w0; break; case 1: w = w1; break; case 2: w = w2; break;
        case 3: w = w3; break; case 4: w = w4; break; default: w = w5; break;
    }
    for (int idx = threadIdx.x; idx < CI * CIN; idx += blockDim.x) {
        int o = idx / CIN;
        int c = idx % CIN;
        g_wT[conv][c][o] = w[o * CIN + c];
    }
}

// ---------------- 1x1 conv ----------------
__global__ __launch_bounds__(256) void conv_kernel(
    const float* __restrict__ x1, const float* __restrict__ x2,
    const float* __restrict__ bv1, const float* __restrict__ bk1, const float* __restrict__ bq1,
    const float* __restrict__ bv2, const float* __restrict__ bk2, const float* __restrict__ bq2)
{
    const int conv = blockIdx.z;
    const int b    = blockIdx.y;
    const int gn0  = blockIdx.x * BN;

    const float* x = (conv < 3) ? x1 : x2;
    const float* bias;
    float* outp;
    bool trans = false;
    switch (conv) {
        case 0: bias = bv1; outp = &g_V1t[0][0][0]; trans = true;  break;
        case 1: bias = bk1; outp = &g_K1[0][0][0];                 break;
        case 2: bias = bq1; outp = &g_Q1[0][0][0];                 break;
        case 3: bias = bv2; outp = &g_V2t[0][0][0]; trans = true;  break;
        case 4: bias = bk2; outp = &g_K2[0][0][0];                 break;
        default: bias = bq2; outp = &g_Q2[0][0][0];                break;
    }

    __shared__ float Ws[32][CI + 4];
    __shared__ float Xs[32][BN + 4];

    const int t  = threadIdx.x;
    const int tx = t & 15;
    const int ty = t >> 4;
    const int o0  = tx * 8;
    const int n0l = ty * 4;

    unsigned long long acc2[4][4];
    #pragma unroll
    for (int p = 0; p < 4; p++) {
        unsigned long long bp = pack2(bias[o0 + 2 * p], bias[o0 + 2 * p + 1]);
        #pragma unroll
        for (int j = 0; j < 4; j++) acc2[p][j] = bp;
    }

    const float* xb = x + (size_t)b * CIN * NPIX + gn0;
    const float* wt = &g_wT[conv][0][0];

    for (int c0 = 0; c0 < CIN; c0 += 32) {
        #pragma unroll
        for (int i = 0; i < 4; i++) {
            int idx4 = t + i * 256;
            int k = idx4 >> 5, o4 = idx4 & 31;
            *(float4*)&Ws[k][o4 * 4] = *(const float4*)&wt[(size_t)(c0 + k) * CI + o4 * 4];
        }
        #pragma unroll
        for (int i = 0; i < 2; i++) {
            int idx4 = t + i * 256;
            int k = idx4 >> 4, n4 = idx4 & 15;
            *(float4*)&Xs[k][n4 * 4] = *(const float4*)&xb[(size_t)(c0 + k) * NPIX + n4 * 4];
        }
        __syncthreads();
        #pragma unroll
        for (int k = 0; k < 32; k++) {
            float4 w0 = *(float4*)&Ws[k][o0];
            float4 w1 = *(float4*)&Ws[k][o0 + 4];
            float4 xv = *(float4*)&Xs[k][n0l];
            unsigned long long wp[4];
            wp[0] = pack2(w0.x, w0.y);  wp[1] = pack2(w0.z, w0.w);
            wp[2] = pack2(w1.x, w1.y);  wp[3] = pack2(w1.z, w1.w);
            float xr[4] = {xv.x, xv.y, xv.z, xv.w};
            #pragma unroll
            for (int j = 0; j < 4; j++) {
                unsigned long long xbcast = pack2(xr[j], xr[j]);
                #pragma unroll
                for (int p = 0; p < 4; p++)
                    acc2[p][j] = fma2(wp[p], xbcast, acc2[p][j]);
            }
        }
        __syncthreads();
    }

    float acc[8][4];
    #pragma unroll
    for (int p = 0; p < 4; p++)
        #pragma unroll
        for (int j = 0; j < 4; j++) {
            float2 v = unpack2(acc2[p][j]);
            acc[2 * p][j]     = v.x;
            acc[2 * p + 1][j] = v.y;
        }

    if (trans) {
        float* vp = outp + (size_t)b * NPIX * CI;
        #pragma unroll
        for (int j = 0; j < 4; j++) {
            size_t gn = gn0 + n0l + j;
            float4 v0 = make_float4(acc[0][j], acc[1][j], acc[2][j], acc[3][j]);
            float4 v1 = make_float4(acc[4][j], acc[5][j], acc[6][j], acc[7][j]);
            *(float4*)&vp[gn * CI + o0]     = v0;
            *(float4*)&vp[gn * CI + o0 + 4] = v1;
        }
    } else {
        float* op = outp + (size_t)b * CI * NPIX + gn0;
        #pragma unroll
        for (int i = 0; i < 8; i++) {
            float4 v = make_float4(acc[i][0], acc[i][1], acc[i][2], acc[i][3]);
            *(float4*)&op[(size_t)(o0 + i) * NPIX + n0l] = v;
        }
    }
}

// ---------------- copy x into first 256 channels of y ----------------
__global__ void copyx_kernel(const float* __restrict__ x1, const float* __restrict__ x2,
                             float* __restrict__ out)
{
    const size_t per = (size_t)NB * CIN * NPIX / 4;
    size_t idx4 = (size_t)blockIdx.x * blockDim.x + threadIdx.x;
    if (idx4 >= 2 * per) return;
    int which = idx4 >= per;
    size_t r  = idx4 - (size_t)which * per;
    size_t bb = r / ((size_t)CIN * NPIX / 4);
    size_t cn = r % ((size_t)CIN * NPIX / 4);
    const float4* src = (const float4*)(which ? x2 : x1);
    float4* dst = (float4*)out + (size_t)which * NB * 384 * NPIX / 4
                               + bb * (384 * NPIX / 4) + cn;
    *dst = src[r];
}

// ---------------- fused attention, 128x128 tiles, 8x8 micro ----------------
// smem: Q[128][132] + Kchunk[32][132] + V[128][132] + S[128][132]
//     = 132*(128+32+128+128) = 54912 floats = 219648 B  (1 CTA/SM)
#define SQ_OFF 0
#define SK_OFF (128*132)
#define SV_OFF (128*132 + 32*132)
#define SS_OFF (128*132 + 32*132 + 128*132)
#define ATTN_SMEM_FLOATS (128*132*3 + 32*132)

__global__ __launch_bounds__(256, 1) void attn_kernel(float* __restrict__ out)
{
    extern __shared__ float sm[];
    float* Qs = sm + SQ_OFF;   // [c=128][n=128 (+4)]
    float* Ks = sm + SK_OFF;   // [c=32 ][m=128 (+4)]
    float* Vs = sm + SV_OFF;   // [m=128][c=128 (+4)]
    float* Ss = sm + SS_OFF;   // [n=128][m=128 (+4)]

    const int gn0 = blockIdx.x * TQ;
    const int b   = blockIdx.y;
    const int dir = blockIdx.z;

    const float* Qg = dir == 0 ? &g_Q1[b][0][0]  : &g_Q2[b][0][0];
    const float* Kg = dir == 0 ? &g_K2[b][0][0]  : &g_K1[b][0][0];
    const float* Vg = dir == 0 ? &g_V2t[b][0][0] : &g_V1t[b][0][0];

    const int t  = threadIdx.x;
    const int tx = t & 15;     // QK: m-group (m0=tx*8) | PV: c-group (c0=tx*8)
    const int ty = t >> 4;     // n-group (n0=ty*8)
    const int m0 = tx * 8;
    const int n0 = ty * 8;

    // stage Q once: 128 rows (c) x 32 float4
    #pragma unroll
    for (int i = 0; i < 16; i++) {
        int idx = t + i * 256;
        int r = idx >> 5, c4 = idx & 31;
        *(float4*)&Qs[r * 132 + c4 * 4] = *(const float4*)&Qg[(size_t)r * NPIX + gn0 + c4 * 4];
    }

    // Fu accumulators: channels (c0+2p, c0+2p+1) x n (n0+j)
    unsigned long long facc2[4][8];
    #pragma unroll
    for (int p = 0; p < 4; p++)
        #pragma unroll
        for (int j = 0; j < 8; j++) facc2[p][j] = 0ull;

    for (int mt = 0; mt < NTA; mt++) {
        const int gm0 = mt * TQ;
        __syncthreads();   // prev PV done reading Ss/Vs (and Q staged on iter 0)

        // stage V tile: 128 rows (m) x 32 float4
        #pragma unroll
        for (int i = 0; i < 16; i++) {
            int idx = t + i * 256;
            int r = idx >> 5, c4 = idx & 31;
            *(float4*)&Vs[r * 132 + c4 * 4] =
                *(const float4*)&Vg[(size_t)(gm0 + r) * CI + c4 * 4];
        }
        // stage K chunk 0: 32 rows (c) x 32 float4
        #pragma unroll
        for (int i = 0; i < 4; i++) {
            int idx = t + i * 256;
            int r = idx >> 5, c4 = idx & 31;
            *(float4*)&Ks[r * 132 + c4 * 4] =
                *(const float4*)&Kg[(size_t)r * NPIX + gm0 + c4 * 4];
        }
        __syncthreads();

        // ---- QK: sacc[8n][8m] over 128 c, in 4 chunks of 32 ----
        unsigned long long sacc2[8][4];
        #pragma unroll
        for (int j = 0; j < 8; j++)
            #pragma unroll
            for (int p = 0; p < 4; p++) sacc2[j][p] = 0ull;

        for (int cc = 0; cc < 4; cc++) {
            #pragma unroll 4
            for (int k = 0; k < 32; k++) {
                float4 q0 = *(float4*)&Qs[(cc * 32 + k) * 132 + n0];
                float4 q1 = *(float4*)&Qs[(cc * 32 + k) * 132 + n0 + 4];
                float4 k0 = *(float4*)&Ks[k * 132 + m0];
                float4 k1 = *(float4*)&Ks[k * 132 + m0 + 4];
                unsigned long long kp[4];
                kp[0] = pack2(k0.x, k0.y); kp[1] = pack2(k0.z, k0.w);
                kp[2] = pack2(k1.x, k1.y); kp[3] = pack2(k1.z, k1.w);
                float qr[8] = {q0.x, q0.y, q0.z, q0.w, q1.x, q1.y, q1.z, q1.w};
                #pragma unroll
                for (int j = 0; j < 8; j++) {
                    unsigned long long qb = pack2(qr[j], qr[j]);
                    #pragma unroll
                    for (int p = 0; p < 4; p++)
                        sacc2[j][p] = fma2(qb, kp[p], sacc2[j][p]);
                }
            }
            if (cc < 3) {
                __syncthreads();   // all warps done with this K chunk
                #pragma unroll
                for (int i = 0; i < 4; i++) {
                    int idx = t + i * 256;
                    int r = idx >> 5, c4 = idx & 31;
                    *(float4*)&Ks[r * 132 + c4 * 4] =
                        *(const float4*)&Kg[(size_t)((cc + 1) * 32 + r) * NPIX + gm0 + c4 * 4];
                }
                __syncthreads();
            }
        }

        // ---- sigmoid + write S[n][m] ----
        #pragma unroll
        for (int j = 0; j < 8; j++) {
            float s[8];
            #pragma unroll
            for (int p = 0; p < 4; p++) {
                float2 v = unpack2(sacc2[j][p]);
                s[2 * p]     = 1.f / (1.f + __expf(-v.x));
                s[2 * p + 1] = 1.f / (1.f + __expf(-v.y));
            }
            *(float4*)&Ss[(n0 + j) * 132 + m0]     = make_float4(s[0], s[1], s[2], s[3]);
            *(float4*)&Ss[(n0 + j) * 132 + m0 + 4] = make_float4(s[4], s[5], s[6], s[7]);
        }
        __syncthreads();

        // ---- PV: facc[8c][8n] += V[m][c] * S[n][m], m = 0..127 ----
        #pragma unroll 1
        for (int m4 = 0; m4 < 32; m4++) {
            const int m = m4 * 4;
            float4 srow[8];
            #pragma unroll
            for (int j = 0; j < 8; j++)
                srow[j] = *(float4*)&Ss[(n0 + j) * 132 + m];
            #pragma unroll
            for (int mm = 0; mm < 4; mm++) {
                float4 v0 = *(float4*)&Vs[(m + mm) * 132 + m0];      // m0==c0 (tx*8)
                float4 v1 = *(float4*)&Vs[(m + mm) * 132 + m0 + 4];
                unsigned long long vp[4];
                vp[0] = pack2(v0.x, v0.y); vp[1] = pack2(v0.z, v0.w);
                vp[2] = pack2(v1.x, v1.y); vp[3] = pack2(v1.z, v1.w);
                #pragma unroll
                for (int j = 0; j < 8; j++) {
                    float sv = f4get(srow[j], mm);
                    unsigned long long sb = pack2(sv, sv);
                    #pragma unroll
                    for (int p = 0; p < 4; p++)
                        facc2[p][j] = fma2(vp[p], sb, facc2[p][j]);
                }
            }
        }
    }

    // ---- epilogue: Fu -> channels [256,384) of y ----
    float acc[8][8];
    #pragma unroll
    for (int p = 0; p < 4; p++)
        #pragma unroll
        for (int j = 0; j < 8; j++) {
            float2 v = unpack2(facc2[p][j]);
            acc[2 * p][j]     = v.x;
            acc[2 * p + 1][j] = v.y;
        }

    float* ob = out + (size_t)dir * NB * 384 * NPIX
                    + (size_t)b * 384 * NPIX + (size_t)256 * NPIX + gn0;
    #pragma unroll
    for (int i = 0; i < 8; i++) {
        *(float4*)&ob[(size_t)(m0 + i) * NPIX + n0]     =
            make_float4(acc[i][0], acc[i][1], acc[i][2], acc[i][3]);
        *(float4*)&ob[(size_t)(m0 + i) * NPIX + n0 + 4] =
            make_float4(acc[i][4], acc[i][5], acc[i][6], acc[i][7]);
    }
}

// ---------------- launch ----------------
extern "C" void kernel_launch(void* const* d_in, const int* in_sizes, int n_in,
                              void* d_out, int out_size)
{
    const float* x1  = (const float*)d_in[0];
    const float* x2  = (const float*)d_in[1];
    const float* wv1 = (const float*)d_in[2];  const float* bv1 = (const float*)d_in[3];
    const float* wk1 = (const float*)d_in[4];  const float* bk1 = (const float*)d_in[5];
    const float* wq1 = (const float*)d_in[6];  const float* bq1 = (const float*)d_in[7];
    const float* wv2 = (const float*)d_in[8];  const float* bv2 = (const float*)d_in[9];
    const float* wk2 = (const float*)d_in[10]; const float* bk2 = (const float*)d_in[11];
    const float* wq2 = (const float*)d_in[12]; const float* bq2 = (const float*)d_in[13];
    float* out = (float*)d_out;

    wtrans_kernel<<<6, 256>>>(wv1, wk1, wq1, wv2, wk2, wq2);

    dim3 cg(NT, NB, 6);
    conv_kernel<<<cg, 256>>>(x1, x2, bv1, bk1, bq1, bv2, bk2, bq2);

    {
        size_t tot4 = 2ull * NB * CIN * NPIX / 4;
        int blocks = (int)((tot4 + 255) / 256);
        copyx_kernel<<<blocks, 256>>>(x1, x2, out);
    }

    size_t smem_bytes = (size_t)ATTN_SMEM_FLOATS * sizeof(float);
    cudaFuncSetAttribute(attn_kernel, cudaFuncAttributeMaxDynamicSharedMemorySize,
                         (int)smem_bytes);
    dim3 ag(NTA, NB, 2);
    attn_kernel<<<ag, 256, smem_bytes>>>(out);
}

// round 11
// speedup vs baseline: 1.9361x; 1.2591x over previous
#include <cuda_runtime.h>

#define NB    8
#define CIN   256
#define CI    128
#define NPIX  2304          // 48*48
#define BN    64            // conv n tile
#define NT    (NPIX/BN)     // 36
#define TQ    128           // attn n/m tile
#define NTA   (NPIX/TQ)     // 18

// ---------------- f32x2 packed math helpers ----------------
__device__ __forceinline__ unsigned long long pack2(float lo, float hi) {
    unsigned long long d;
    asm("mov.b64 %0, {%1, %2};"
        : "=l"(d) : "r"(__float_as_uint(lo)), "r"(__float_as_uint(hi)));
    return d;
}
__device__ __forceinline__ unsigned long long fma2(unsigned long long a,
                                                   unsigned long long b,
                                                   unsigned long long c) {
    unsigned long long d;
    asm("fma.rn.f32x2 %0, %1, %2, %3;" : "=l"(d) : "l"(a), "l"(b), "l"(c));
    return d;
}
__device__ __forceinline__ float2 unpack2(unsigned long long v) {
    unsigned int lo, hi;
    asm("mov.b64 {%0, %1}, %2;" : "=r"(lo), "=r"(hi) : "l"(v));
    return make_float2(__uint_as_float(lo), __uint_as_float(hi));
}
__device__ __forceinline__ float f4get(const float4& v, int i) {
    return i == 0 ? v.x : (i == 1 ? v.y : (i == 2 ? v.z : v.w));
}

// ---------------- cp.async helpers ----------------
__device__ __forceinline__ unsigned int s2u(const void* p) {
    unsigned int a;
    asm("{ .reg .u64 t; cvta.to.shared.u64 t, %1; cvt.u32.u64 %0, t; }"
        : "=r"(a) : "l"(p));
    return a;
}
__device__ __forceinline__ void cp16(unsigned int dst, const void* src) {
    asm volatile("cp.async.cg.shared.global [%0], [%1], 16;" :: "r"(dst), "l"(src));
}
__device__ __forceinline__ void cp_commit() {
    asm volatile("cp.async.commit_group;");
}
template <int N> __device__ __forceinline__ void cp_wait() {
    asm volatile("cp.async.wait_group %0;" :: "n"(N));
}

// ---------------- scratch ----------------
__device__ float g_Q1[NB][CI][NPIX];
__device__ float g_K1[NB][CI][NPIX];
__device__ float g_V1t[NB][NPIX][CI];   // [n][c]
__device__ float g_Q2[NB][CI][NPIX];
__device__ float g_K2[NB][CI][NPIX];
__device__ float g_V2t[NB][NPIX][CI];
__device__ float g_wT[6][CIN][CI];      // [c][o]

// ---------------- weight transpose ----------------
__global__ void wtrans_kernel(const float* __restrict__ w0, const float* __restrict__ w1,
                              const float* __restrict__ w2, const float* __restrict__ w3,
                              const float* __restrict__ w4, const float* __restrict__ w5)
{
    int conv = blockIdx.x;
    const float* w;
    switch (conv) {
        case 0: w = w0; break; case 1: w = w1; break; case 2: w = w2; break;
        case 3: w = w3; break; case 4: w = w4; break; default: w = w5; break;
    }
    for (int idx = threadIdx.x; idx < CI * CIN; idx += blockDim.x) {
        int o = idx / CIN;
        int c = idx % CIN;
        g_wT[conv][c][o] = w[o * CIN + c];
    }
}

// ---------------- 1x1 conv, split-o micro-tile (conflict-free) ----------------
__global__ __launch_bounds__(256) void conv_kernel(
    const float* __restrict__ x1, const float* __restrict__ x2,
    const float* __restrict__ bv1, const float* __restrict__ bk1, const float* __restrict__ bq1,
    const float* __restrict__ bv2, const float* __restrict__ bk2, const float* __restrict__ bq2)
{
    const int conv = blockIdx.z;
    const int b    = blockIdx.y;
    const int gn0  = blockIdx.x * BN;

    const float* x = (conv < 3) ? x1 : x2;
    const float* bias;
    float* outp;
    bool trans = false;
    switch (conv) {
        case 0: bias = bv1; outp = &g_V1t[0][0][0]; trans = true;  break;
        case 1: bias = bk1; outp = &g_K1[0][0][0];                 break;
        case 2: bias = bq1; outp = &g_Q1[0][0][0];                 break;
        case 3: bias = bv2; outp = &g_V2t[0][0][0]; trans = true;  break;
        case 4: bias = bk2; outp = &g_K2[0][0][0];                 break;
        default: bias = bq2; outp = &g_Q2[0][0][0];                break;
    }

    __shared__ float Ws[32][CI];   // [k][o]
    __shared__ float Xs[32][BN];   // [k][n]

    const int t  = threadIdx.x;
    const int tx = t & 15;
    const int ty = t >> 4;
    const int oA  = tx * 4;        // o channels tx*4..+3
    const int oB  = 64 + tx * 4;   // and 64+tx*4..+3
    const int n0l = ty * 4;

    unsigned long long acc2[4][4];
    #pragma unroll
    for (int p = 0; p < 4; p++) {
        int ob0 = (p < 2) ? (oA + 2 * p) : (oB + 2 * (p - 2));
        unsigned long long bp = pack2(bias[ob0], bias[ob0 + 1]);
        #pragma unroll
        for (int j = 0; j < 4; j++) acc2[p][j] = bp;
    }

    const float* xb = x + (size_t)b * CIN * NPIX + gn0;
    const float* wt = &g_wT[conv][0][0];

    for (int c0 = 0; c0 < CIN; c0 += 32) {
        #pragma unroll
        for (int i = 0; i < 4; i++) {
            int idx4 = t + i * 256;
            int k = idx4 >> 5, o4 = idx4 & 31;
            *(float4*)&Ws[k][o4 * 4] = *(const float4*)&wt[(size_t)(c0 + k) * CI + o4 * 4];
        }
        #pragma unroll
        for (int i = 0; i < 2; i++) {
            int idx4 = t + i * 256;
            int k = idx4 >> 4, n4 = idx4 & 15;
            *(float4*)&Xs[k][n4 * 4] = *(const float4*)&xb[(size_t)(c0 + k) * NPIX + n4 * 4];
        }
        __syncthreads();
        #pragma unroll
        for (int k = 0; k < 32; k++) {
            float4 w0 = *(float4*)&Ws[k][oA];
            float4 w1 = *(float4*)&Ws[k][oB];
            float4 xv = *(float4*)&Xs[k][n0l];
            unsigned long long wp[4];
            wp[0] = pack2(w0.x, w0.y);  wp[1] = pack2(w0.z, w0.w);
            wp[2] = pack2(w1.x, w1.y);  wp[3] = pack2(w1.z, w1.w);
            float xr[4] = {xv.x, xv.y, xv.z, xv.w};
            #pragma unroll
            for (int j = 0; j < 4; j++) {
                unsigned long long xbcast = pack2(xr[j], xr[j]);
                #pragma unroll
                for (int p = 0; p < 4; p++)
                    acc2[p][j] = fma2(wp[p], xbcast, acc2[p][j]);
            }
        }
        __syncthreads();
    }

    if (trans) {
        float* vp = outp + (size_t)b * NPIX * CI;
        #pragma unroll
        for (int j = 0; j < 4; j++) {
            size_t gn = gn0 + n0l + j;
            float2 a0 = unpack2(acc2[0][j]);
            float2 a1 = unpack2(acc2[1][j]);
            float2 a2 = unpack2(acc2[2][j]);
            float2 a3 = unpack2(acc2[3][j]);
            *(float4*)&vp[gn * CI + oA] = make_float4(a0.x, a0.y, a1.x, a1.y);
            *(float4*)&vp[gn * CI + oB] = make_float4(a2.x, a2.y, a3.x, a3.y);
        }
    } else {
        float* op = outp + (size_t)b * CI * NPIX + gn0;
        float acc[8][4];
        #pragma unroll
        for (int p = 0; p < 4; p++)
            #pragma unroll
            for (int j = 0; j < 4; j++) {
                float2 v = unpack2(acc2[p][j]);
                acc[2 * p][j]     = v.x;
                acc[2 * p + 1][j] = v.y;
            }
        #pragma unroll
        for (int i = 0; i < 4; i++) {
            *(float4*)&op[(size_t)(oA + i) * NPIX + n0l] =
                make_float4(acc[i][0], acc[i][1], acc[i][2], acc[i][3]);
            *(float4*)&op[(size_t)(oB + i) * NPIX + n0l] =
                make_float4(acc[4 + i][0], acc[4 + i][1], acc[4 + i][2], acc[4 + i][3]);
        }
    }
}

// ---------------- copy x into first 256 channels of y ----------------
__global__ void copyx_kernel(const float* __restrict__ x1, const float* __restrict__ x2,
                             float* __restrict__ out)
{
    const size_t per = (size_t)NB * CIN * NPIX / 4;
    size_t idx4 = (size_t)blockIdx.x * blockDim.x + threadIdx.x;
    if (idx4 >= 2 * per) return;
    int which = idx4 >= per;
    size_t r  = idx4 - (size_t)which * per;
    size_t bb = r / ((size_t)CIN * NPIX / 4);
    size_t cn = r % ((size_t)CIN * NPIX / 4);
    const float4* src = (const float4*)(which ? x2 : x1);
    float4* dst = (float4*)out + (size_t)which * NB * 384 * NPIX / 4
                               + bb * (384 * NPIX / 4) + cn;
    *dst = src[r];
}

// ---------------- fused attention: 128x128 tiles, 512 threads ----------------
// smem (floats, stride 128, no padding needed — all accesses row-contiguous
// or broadcast): Q[128][128] + V[128][128] + S[128][128] + Kb[2][32][128]
// = 57344 floats = 229376 B (1 CTA/SM)
#define SQ_OFF 0
#define SV_OFF (128*128)
#define SS_OFF (2*128*128)
#define SKB_OFF (3*128*128)
#define ATTN_SMEM_FLOATS (3*128*128 + 2*32*128)

__global__ __launch_bounds__(512, 1) void attn_kernel(float* __restrict__ out)
{
    extern __shared__ float sm[];
    float* Qs  = sm + SQ_OFF;            // [c=128][n=128]
    float* Vs  = sm + SV_OFF;            // [m=128][c=128]
    float* Ss  = sm + SS_OFF;            // [n=128][m=128]
    float* Kb[2] = { sm + SKB_OFF, sm + SKB_OFF + 32 * 128 };   // [c=32][m=128]

    const int gn0 = blockIdx.x * TQ;
    const int b   = blockIdx.y;
    const int dir = blockIdx.z;

    const float* Qg = dir == 0 ? &g_Q1[b][0][0]  : &g_Q2[b][0][0];
    const float* Kg = dir == 0 ? &g_K2[b][0][0]  : &g_K1[b][0][0];
    const float* Vg = dir == 0 ? &g_V2t[b][0][0] : &g_V1t[b][0][0];

    const int t  = threadIdx.x;
    const int tx = t & 15;     // 0..15
    const int ty = t >> 4;     // 0..31
    const int mA = tx * 4;     // QK m (and PV c) group A
    const int mB = 64 + tx * 4;
    const int n0 = ty * 4;     // n group

    // stage Q once (plain loads): 4096 float4 / 512 = 8 iters
    #pragma unroll
    for (int i = 0; i < 8; i++) {
        int idx = t + i * 512;
        int r = idx >> 5, c4 = idx & 31;
        *(float4*)&Qs[r * 128 + c4 * 4] = *(const float4*)&Qg[(size_t)r * NPIX + gn0 + c4 * 4];
    }

    // Fu accumulators: p0,1 -> channels mA+2p.. ; p2,3 -> mB+2(p-2)..
    unsigned long long facc2[4][4];
    #pragma unroll
    for (int p = 0; p < 4; p++)
        #pragma unroll
        for (int j = 0; j < 4; j++) facc2[p][j] = 0ull;

    const unsigned int kb_u[2] = { s2u(Kb[0]), s2u(Kb[1]) };
    const unsigned int vs_u = s2u(Vs);

    for (int mt = 0; mt < NTA; mt++) {
        const int gm0 = mt * TQ;
        __syncthreads();   // prev PV done reading Ss/Vs/Kb (and Q staged on iter 0)

        // prefetch K chunk 0 (g0) and V tile (g1) via cp.async
        {
            // K chunk 0: 1024 float4 / 512 = 2 per thread
            #pragma unroll
            for (int i = 0; i < 2; i++) {
                int idx = t + i * 512;
                int r = idx >> 5, c4 = idx & 31;
                cp16(kb_u[0] + (r * 128 + c4 * 4) * 4,
                     &Kg[(size_t)r * NPIX + gm0 + c4 * 4]);
            }
            cp_commit();
            // V: 4096 float4 / 512 = 8 per thread
            #pragma unroll
            for (int i = 0; i < 8; i++) {
                int idx = t + i * 512;
                int r = idx >> 5, c4 = idx & 31;
                cp16(vs_u + (r * 128 + c4 * 4) * 4,
                     &Vg[(size_t)(gm0 + r) * CI + c4 * 4]);
            }
            cp_commit();
        }

        // ---- QK: sacc[4n][8m] over 128 c, 4 chunks of 32, double-buffered ----
        unsigned long long sacc2[4][4];
        #pragma unroll
        for (int j = 0; j < 4; j++)
            #pragma unroll
            for (int p = 0; p < 4; p++) sacc2[j][p] = 0ull;

        #pragma unroll
        for (int cc = 0; cc < 4; cc++) {
            if (cc < 3) {   // prefetch next chunk into other buffer
                #pragma unroll
                for (int i = 0; i < 2; i++) {
                    int idx = t + i * 512;
                    int r = idx >> 5, c4 = idx & 31;
                    cp16(kb_u[(cc + 1) & 1] + (r * 128 + c4 * 4) * 4,
                         &Kg[(size_t)((cc + 1) * 32 + r) * NPIX + gm0 + c4 * 4]);
                }
                cp_commit();
            }
            if (cc == 0)      cp_wait<2>();
            else if (cc < 3)  cp_wait<1>();
            else              cp_wait<0>();
            __syncthreads();

            const float* K = Kb[cc & 1];
            #pragma unroll 4
            for (int k = 0; k < 32; k++) {
                float4 qv = *(float4*)&Qs[(cc * 32 + k) * 128 + n0];
                float4 k0 = *(float4*)&K[k * 128 + mA];
                float4 k1 = *(float4*)&K[k * 128 + mB];
                unsigned long long kp[4];
                kp[0] = pack2(k0.x, k0.y); kp[1] = pack2(k0.z, k0.w);
                kp[2] = pack2(k1.x, k1.y); kp[3] = pack2(k1.z, k1.w);
                float qr[4] = {qv.x, qv.y, qv.z, qv.w};
                #pragma unroll
                for (int j = 0; j < 4; j++) {
                    unsigned long long qb = pack2(qr[j], qr[j]);
                    #pragma unroll
                    for (int p = 0; p < 4; p++)
                        sacc2[j][p] = fma2(qb, kp[p], sacc2[j][p]);
                }
            }
            if (cc < 3) __syncthreads();   // done reading Kb[cc&1] before its refill
        }

        // ---- sigmoid + write S[n][m] (conflict-free: 16B-contiguous lanes) ----
        #pragma unroll
        for (int j = 0; j < 4; j++) {
            float s[8];
            #pragma unroll
            for (int p = 0; p < 4; p++) {
                float2 v = unpack2(sacc2[j][p]);
                s[2 * p]     = __fdividef(1.f, 1.f + __expf(-v.x));
                s[2 * p + 1] = __fdividef(1.f, 1.f + __expf(-v.y));
            }
            *(float4*)&Ss[(n0 + j) * 128 + mA] = make_float4(s[0], s[1], s[2], s[3]);
            *(float4*)&Ss[(n0 + j) * 128 + mB] = make_float4(s[4], s[5], s[6], s[7]);
        }
        __syncthreads();

        // ---- PV: facc[8c][4n] += V[m][c] * S[n][m], m = 0..127 ----
        #pragma unroll 2
        for (int m4 = 0; m4 < 32; m4++) {
            const int m = m4 * 4;
            float4 srow[4];
            #pragma unroll
            for (int j = 0; j < 4; j++)
                srow[j] = *(float4*)&Ss[(n0 + j) * 128 + m];      // broadcast
            #pragma unroll
            for (int mm = 0; mm < 4; mm++) {
                float4 v0 = *(float4*)&Vs[(m + mm) * 128 + mA];
                float4 v1 = *(float4*)&Vs[(m + mm) * 128 + mB];
                unsigned long long vp[4];
                vp[0] = pack2(v0.x, v0.y); vp[1] = pack2(v0.z, v0.w);
                vp[2] = pack2(v1.x, v1.y); vp[3] = pack2(v1.z, v1.w);
                #pragma unroll
                for (int j = 0; j < 4; j++) {
                    float sv = f4get(srow[j], mm);
                    unsigned long long sb = pack2(sv, sv);
                    #pragma unroll
                    for (int p = 0; p < 4; p++)
                        facc2[p][j] = fma2(vp[p], sb, facc2[p][j]);
                }
            }
        }
    }

    // ---- epilogue: Fu -> channels [256,384) of y ----
    float acc[8][4];
    #pragma unroll
    for (int p = 0; p < 4; p++)
        #pragma unroll
        for (int j = 0; j < 4; j++) {
            float2 v = unpack2(facc2[p][j]);
            acc[2 * p][j]     = v.x;
            acc[2 * p + 1][j] = v.y;
        }

    float* ob = out + (size_t)dir * NB * 384 * NPIX
                    + (size_t)b * 384 * NPIX + (size_t)256 * NPIX + gn0;
    #pragma unroll
    for (int i = 0; i < 4; i++) {
        *(float4*)&ob[(size_t)(mA + i) * NPIX + n0] =
            make_float4(acc[i][0], acc[i][1], acc[i][2], acc[i][3]);
        *(float4*)&ob[(size_t)(mB + i) * NPIX + n0] =
            make_float4(acc[4 + i][0], acc[4 + i][1], acc[4 + i][2], acc[4 + i][3]);
    }
}

// ---------------- launch ----------------
extern "C" void kernel_launch(void* const* d_in, const int* in_sizes, int n_in,
                              void* d_out, int out_size)
{
    const float* x1  = (const float*)d_in[0];
    const float* x2  = (const float*)d_in[1];
    const float* wv1 = (const float*)d_in[2];  const float* bv1 = (const float*)d_in[3];
    const float* wk1 = (const float*)d_in[4];  const float* bk1 = (const float*)d_in[5];
    const float* wq1 = (const float*)d_in[6];  const float* bq1 = (const float*)d_in[7];
    const float* wv2 = (const float*)d_in[8];  const float* bv2 = (const float*)d_in[9];
    const float* wk2 = (const float*)d_in[10]; const float* bk2 = (const float*)d_in[11];
    const float* wq2 = (const float*)d_in[12]; const float* bq2 = (const float*)d_in[13];
    float* out = (float*)d_out;

    wtrans_kernel<<<6, 256>>>(wv1, wk1, wq1, wv2, wk2, wq2);

    dim3 cg(NT, NB, 6);
    conv_kernel<<<cg, 256>>>(x1, x2, bv1, bk1, bq1, bv2, bk2, bq2);

    {
        size_t tot4 = 2ull * NB * CIN * NPIX / 4;
        int blocks = (int)((tot4 + 255) / 256);
        copyx_kernel<<<blocks, 256>>>(x1, x2, out);
    }

    size_t smem_bytes = (size_t)ATTN_SMEM_FLOATS * sizeof(float);
    cudaFuncSetAttribute(attn_kernel, cudaFuncAttributeMaxDynamicSharedMemorySize,
                         (int)smem_bytes);
    dim3 ag(NTA, NB, 2);
    attn_kernel<<<ag, 512, smem_bytes>>>(out);
}

// round 13
// speedup vs baseline: 3.6491x; 1.8848x over previous
#include <cuda_runtime.h>
#include <cuda_fp16.h>

#define NB    8
#define CIN   256
#define CI    128
#define NPIX  2304          // 48*48
#define BN    64            // conv n tile
#define NT    (NPIX/BN)     // 36
#define TN    128           // attn n tile per CTA
#define TM    64            // attn m tile
#define NNT   (NPIX/TN)     // 18
#define NMT   (NPIX/TM)     // 36

#define QSTR  136           // halves stride for 128-col tiles (272B: 16B-aligned, 4-bank rot)
#define VSTR  88            // halves stride for 64-col tiles (176B: 16B-aligned, 12-bank rot)

// smem layout in halves
#define QH_H  0
#define QL_H  (128*QSTR)
#define KH_H  (2*128*QSTR)
#define KL_H  (KH_H + 64*QSTR)
#define VH_H  (KL_H + 64*QSTR)
#define VL_H  (VH_H + 128*VSTR)
#define SH_H  (VL_H + 128*VSTR)
#define SL_H  (SH_H + 128*VSTR)
#define SMEM_HALVES (SL_H + 128*VSTR)      // 97280 halves = 194560 B

// ---------------- f32x2 packed helpers (conv) ----------------
__device__ __forceinline__ unsigned long long pack2(float lo, float hi) {
    unsigned long long d;
    asm("mov.b64 %0, {%1, %2};"
        : "=l"(d) : "r"(__float_as_uint(lo)), "r"(__float_as_uint(hi)));
    return d;
}
__device__ __forceinline__ unsigned long long fma2(unsigned long long a,
                                                   unsigned long long b,
                                                   unsigned long long c) {
    unsigned long long d;
    asm("fma.rn.f32x2 %0, %1, %2, %3;" : "=l"(d) : "l"(a), "l"(b), "l"(c));
    return d;
}
__device__ __forceinline__ float2 unpack2(unsigned long long v) {
    unsigned int lo, hi;
    asm("mov.b64 {%0, %1}, %2;" : "=r"(lo), "=r"(hi) : "l"(v));
    return make_float2(__uint_as_float(lo), __uint_as_float(hi));
}

// ---------------- cp.async ----------------
__device__ __forceinline__ unsigned s2u(const void* p) {
    unsigned a;
    asm("{ .reg .u64 t; cvta.to.shared.u64 t, %1; cvt.u32.u64 %0, t; }"
        : "=r"(a) : "l"(p));
    return a;
}
__device__ __forceinline__ void cp16(unsigned dst, const void* src) {
    asm volatile("cp.async.cg.shared.global [%0], [%1], 16;" :: "r"(dst), "l"(src));
}
__device__ __forceinline__ void cp_commit() { asm volatile("cp.async.commit_group;"); }
__device__ __forceinline__ void cp_wait0()  { asm volatile("cp.async.wait_group 0;" ::: "memory"); }
__device__ __forceinline__ void cp_wait1()  { asm volatile("cp.async.wait_group 1;" ::: "memory"); }

// ---------------- mma.sync + ldmatrix ----------------
__device__ __forceinline__ void ldm4(unsigned* r, unsigned addr) {
    asm volatile("ldmatrix.sync.aligned.m8n8.x4.shared.b16 {%0,%1,%2,%3}, [%4];"
        : "=r"(r[0]), "=r"(r[1]), "=r"(r[2]), "=r"(r[3]) : "r"(addr));
}
// A fragment (16x16, row-major): regs a0..a3
__device__ __forceinline__ void ldmA(unsigned* r, unsigned base, int offh,
                                     int r0, int c0, int stride, int lane) {
    int g = lane >> 3, rr = lane & 7;
    int row = r0 + rr + ((g & 1) << 3);
    int col = c0 + ((g >> 1) << 3);
    ldm4(r, base + (unsigned)(offh + row * stride + col) * 2);
}
// B double-fragment: two 16x8 col-major frags (output cols r0..+15), k = c0..+15
__device__ __forceinline__ void ldmB(unsigned* r, unsigned base, int offh,
                                     int r0, int c0, int stride, int lane) {
    int g = lane >> 3, rr = lane & 7;
    int row = r0 + rr + ((g >> 1) << 3);
    int col = c0 + ((g & 1) << 3);
    ldm4(r, base + (unsigned)(offh + row * stride + col) * 2);
}
__device__ __forceinline__ void mma16816(float* c, const unsigned* a, const unsigned* b) {
    asm volatile("mma.sync.aligned.m16n8k16.row.col.f32.f16.f16.f32 "
        "{%0,%1,%2,%3}, {%4,%5,%6,%7}, {%8,%9}, {%0,%1,%2,%3};"
        : "+f"(c[0]), "+f"(c[1]), "+f"(c[2]), "+f"(c[3])
        : "r"(a[0]), "r"(a[1]), "r"(a[2]), "r"(a[3]), "r"(b[0]), "r"(b[1]));
}

// ---------------- scratch (indexed by attn dir-of-use) ----------------
__device__ __half g_Qh[2][NB][NPIX][CI];   // [pix n][c]
__device__ __half g_Ql[2][NB][NPIX][CI];
__device__ __half g_Kh[2][NB][NPIX][CI];   // [pix m][c]
__device__ __half g_Kl[2][NB][NPIX][CI];
__device__ __half g_Vh[2][NB][CI][NPIX];   // [c][pix m]
__device__ __half g_Vl[2][NB][CI][NPIX];
__device__ float  g_wT[6][CIN][CI];        // [c][o]

// ---------------- weight transpose ----------------
__global__ void wtrans_kernel(const float* __restrict__ w0, const float* __restrict__ w1,
                              const float* __restrict__ w2, const float* __restrict__ w3,
                              const float* __restrict__ w4, const float* __restrict__ w5)
{
    int conv = blockIdx.x;
    const float* w;
    switch (conv) {
        case 0: w = w0; break; case 1: w = w1; break; case 2: w = w2; break;
        case 3: w = w3; break; case 4: w = w4; break; default: w = w5; break;
    }
    for (int idx = threadIdx.x; idx < CI * CIN; idx += blockDim.x) {
        int o = idx / CIN;
        int c = idx % CIN;
        g_wT[conv][c][o] = w[o * CIN + c];
    }
}

// ---------------- 1x1 conv (fp32 math; fp16 hi/lo epilogue) ----------------
__global__ __launch_bounds__(256) void conv_kernel(
    const float* __restrict__ x1, const float* __restrict__ x2,
    const float* __restrict__ bv1, const float* __restrict__ bk1, const float* __restrict__ bq1,
    const float* __restrict__ bv2, const float* __restrict__ bk2, const float* __restrict__ bq2)
{
    const int conv = blockIdx.z;
    const int b    = blockIdx.y;
    const int gn0  = blockIdx.x * BN;

    const float* x = (conv < 3) ? x1 : x2;
    const float* bias;
    __half *oH, *oL;
    bool vmode = false;
    switch (conv) {
        case 0: bias = bv1; oH = &g_Vh[1][b][0][0]; oL = &g_Vl[1][b][0][0]; vmode = true; break;
        case 3: bias = bv2; oH = &g_Vh[0][b][0][0]; oL = &g_Vl[0][b][0][0]; vmode = true; break;
        case 1: bias = bk1; oH = &g_Kh[1][b][0][0]; oL = &g_Kl[1][b][0][0]; break;
        case 4: bias = bk2; oH = &g_Kh[0][b][0][0]; oL = &g_Kl[0][b][0][0]; break;
        case 2: bias = bq1; oH = &g_Qh[0][b][0][0]; oL = &g_Ql[0][b][0][0]; break;
        default: bias = bq2; oH = &g_Qh[1][b][0][0]; oL = &g_Ql[1][b][0][0]; break;
    }

    __shared__ float Ws[32][CI];
    __shared__ float Xs[32][BN];

    const int t  = threadIdx.x;
    const int tx = t & 15;
    const int ty = t >> 4;
    const int oA  = tx * 4;
    const int oB  = 64 + tx * 4;
    const int n0l = ty * 4;

    unsigned long long acc2[4][4];
    #pragma unroll
    for (int p = 0; p < 4; p++) {
        int ob0 = (p < 2) ? (oA + 2 * p) : (oB + 2 * (p - 2));
        unsigned long long bp = pack2(bias[ob0], bias[ob0 + 1]);
        #pragma unroll
        for (int j = 0; j < 4; j++) acc2[p][j] = bp;
    }

    const float* xb = x + (size_t)b * CIN * NPIX + gn0;
    const float* wt = &g_wT[conv][0][0];

    for (int c0 = 0; c0 < CIN; c0 += 32) {
        #pragma unroll
        for (int i = 0; i < 4; i++) {
            int idx4 = t + i * 256;
            int k = idx4 >> 5, o4 = idx4 & 31;
            *(float4*)&Ws[k][o4 * 4] = *(const float4*)&wt[(size_t)(c0 + k) * CI + o4 * 4];
        }
        #pragma unroll
        for (int i = 0; i < 2; i++) {
            int idx4 = t + i * 256;
            int k = idx4 >> 4, n4 = idx4 & 15;
            *(float4*)&Xs[k][n4 * 4] = *(const float4*)&xb[(size_t)(c0 + k) * NPIX + n4 * 4];
        }
        __syncthreads();
        #pragma unroll
        for (int k = 0; k < 32; k++) {
            float4 w0 = *(float4*)&Ws[k][oA];
            float4 w1 = *(float4*)&Ws[k][oB];
            float4 xv = *(float4*)&Xs[k][n0l];
            unsigned long long wp[4];
            wp[0] = pack2(w0.x, w0.y);  wp[1] = pack2(w0.z, w0.w);
            wp[2] = pack2(w1.x, w1.y);  wp[3] = pack2(w1.z, w1.w);
            float xr[4] = {xv.x, xv.y, xv.z, xv.w};
            #pragma unroll
            for (int j = 0; j < 4; j++) {
                unsigned long long xbcast = pack2(xr[j], xr[j]);
                #pragma unroll
                for (int p = 0; p < 4; p++)
                    acc2[p][j] = fma2(wp[p], xbcast, acc2[p][j]);
            }
        }
        __syncthreads();
    }

    float acc[8][4];
    #pragma unroll
    for (int p = 0; p < 4; p++)
        #pragma unroll
        for (int j = 0; j < 4; j++) {
            float2 v = unpack2(acc2[p][j]);
            acc[2 * p][j]     = v.x;   // channel groups: 0-3 -> oA+0..3, 4-7 -> oB+0..3
            acc[2 * p + 1][j] = v.y;
        }

    if (!vmode) {
        // Q/K: transposed [pix][c], fp16 hi/lo
        #pragma unroll
        for (int j = 0; j < 4; j++) {
            size_t gn = gn0 + n0l + j;
            __half h[8], l[8];
            #pragma unroll
            for (int i = 0; i < 8; i++) {
                float v = acc[i][j];
                h[i] = __float2half_rn(v);
                l[i] = __float2half_rn(v - __half2float(h[i]));
            }
            *(half2*)&oH[gn * CI + oA]     = __halves2half2(h[0], h[1]);
            *(half2*)&oH[gn * CI + oA + 2] = __halves2half2(h[2], h[3]);
            *(half2*)&oH[gn * CI + oB]     = __halves2half2(h[4], h[5]);
            *(half2*)&oH[gn * CI + oB + 2] = __halves2half2(h[6], h[7]);
            *(half2*)&oL[gn * CI + oA]     = __halves2half2(l[0], l[1]);
            *(half2*)&oL[gn * CI + oA + 2] = __halves2half2(l[2], l[3]);
            *(half2*)&oL[gn * CI + oB]     = __halves2half2(l[4], l[5]);
            *(half2*)&oL[gn * CI + oB + 2] = __halves2half2(l[6], l[7]);
        }
    } else {
        // V: [c][pix], fp16 hi/lo
        #pragma unroll
        for (int i = 0; i < 8; i++) {
            int c = (i < 4) ? (oA + i) : (oB + i - 4);
            __half h[4], l[4];
            #pragma unroll
            for (int j = 0; j < 4; j++) {
                float v = acc[i][j];
                h[j] = __float2half_rn(v);
                l[j] = __float2half_rn(v - __half2float(h[j]));
            }
            size_t o = (size_t)c * NPIX + gn0 + n0l;
            *(half2*)&oH[o]     = __halves2half2(h[0], h[1]);
            *(half2*)&oH[o + 2] = __halves2half2(h[2], h[3]);
            *(half2*)&oL[o]     = __halves2half2(l[0], l[1]);
            *(half2*)&oL[o + 2] = __halves2half2(l[2], l[3]);
        }
    }
}

// ---------------- copy x into first 256 channels of y ----------------
__global__ void copyx_kernel(const float* __restrict__ x1, const float* __restrict__ x2,
                             float* __restrict__ out)
{
    const size_t per = (size_t)NB * CIN * NPIX / 4;
    size_t idx4 = (size_t)blockIdx.x * blockDim.x + threadIdx.x;
    if (idx4 >= 2 * per) return;
    int which = idx4 >= per;
    size_t r  = idx4 - (size_t)which * per;
    size_t bb = r / ((size_t)CIN * NPIX / 4);
    size_t cn = r % ((size_t)CIN * NPIX / 4);
    const float4* src = (const float4*)(which ? x2 : x1);
    float4* dst = (float4*)out + (size_t)which * NB * 384 * NPIX / 4
                               + bb * (384 * NPIX / 4) + cn;
    *dst = src[r];
}

// ---------------- mma.sync fp16 hi/lo attention ----------------
__global__ __launch_bounds__(512, 1) void attn_kernel(float* __restrict__ out)
{
    extern __shared__ __half smh[];
    const unsigned base = s2u(smh);
    const int t    = threadIdx.x;
    const int lane = t & 31;
    const int wid  = t >> 5;

    const int gn0 = blockIdx.x * TN;
    const int b   = blockIdx.y;
    const int dir = blockIdx.z;

    const __half* Qhg = &g_Qh[dir][b][0][0];
    const __half* Qlg = &g_Ql[dir][b][0][0];
    const __half* Khg = &g_Kh[dir][b][0][0];
    const __half* Klg = &g_Kl[dir][b][0][0];
    const __half* Vhg = &g_Vh[dir][b][0][0];
    const __half* Vlg = &g_Vl[dir][b][0][0];

    // warp tiling: QK -> n block 16 (wid&7), m block 32 (wid>>3)
    //              PV -> c block 16 (wid&7), n block 64 (wid>>3)
    const int wlo = wid & 7, whi = wid >> 3;
    const int n0q = wlo * 16, m0w = whi * 32;
    const int c0w = wlo * 16, n0w = whi * 64;

    // stage Q hi/lo [128][136] (plain 16B copies)
    #pragma unroll
    for (int i = 0; i < 8; i++) {
        int j = t + (i & 3) * 512;
        int r = j >> 4, ch = j & 15;
        if (i < 4)
            *(uint4*)(smh + QH_H + r * QSTR + ch * 8) =
                *(const uint4*)(Qhg + (size_t)(gn0 + r) * CI + ch * 8);
        else
            *(uint4*)(smh + QL_H + r * QSTR + ch * 8) =
                *(const uint4*)(Qlg + (size_t)(gn0 + r) * CI + ch * 8);
    }

    float facc[8][4];
    #pragma unroll
    for (int j = 0; j < 8; j++)
        #pragma unroll
        for (int p = 0; p < 4; p++) facc[j][p] = 0.f;

    for (int mt = 0; mt < NMT; mt++) {
        const int gm0 = mt * TM;
        __syncthreads();   // prev-iter consumers done (and Q staged on iter 0)

        // group 1: K hi/lo [64][128]
        #pragma unroll
        for (int i = 0; i < 2; i++) {
            int j = t + i * 512;
            int r = j >> 4, ch = j & 15;
            cp16(base + (unsigned)(KH_H + r * QSTR + ch * 8) * 2,
                 Khg + (size_t)(gm0 + r) * CI + ch * 8);
            cp16(base + (unsigned)(KL_H + r * QSTR + ch * 8) * 2,
                 Klg + (size_t)(gm0 + r) * CI + ch * 8);
        }
        cp_commit();
        // group 2: V hi/lo [128][64]
        #pragma unroll
        for (int i = 0; i < 2; i++) {
            int j = t + i * 512;
            int r = j >> 3, ch = j & 7;
            cp16(base + (unsigned)(VH_H + r * VSTR + ch * 8) * 2,
                 Vhg + (size_t)r * NPIX + gm0 + ch * 8);
            cp16(base + (unsigned)(VL_H + r * VSTR + ch * 8) * 2,
                 Vlg + (size_t)r * NPIX + gm0 + ch * 8);
        }
        cp_commit();
        cp_wait1();        // K ready
        __syncthreads();

        // ---- QK: S[16n x 32m] per warp; Qh.Kh + Qh.Kl + Ql.Kh ----
        float sacc[4][4];
        #pragma unroll
        for (int j = 0; j < 4; j++)
            #pragma unroll
            for (int p = 0; p < 4; p++) sacc[j][p] = 0.f;

        #pragma unroll
        for (int kk = 0; kk < 8; kk++) {
            const int c0 = kk * 16;
            unsigned aH[4], aL[4];
            ldmA(aH, base, QH_H, n0q, c0, QSTR, lane);
            ldmA(aL, base, QL_H, n0q, c0, QSTR, lane);
            unsigned bH0[4], bH1[4], bL0[4], bL1[4];
            ldmB(bH0, base, KH_H, m0w,      c0, QSTR, lane);
            ldmB(bH1, base, KH_H, m0w + 16, c0, QSTR, lane);
            ldmB(bL0, base, KL_H, m0w,      c0, QSTR, lane);
            ldmB(bL1, base, KL_H, m0w + 16, c0, QSTR, lane);
            #pragma unroll
            for (int j = 0; j < 4; j++) {
                const unsigned* bh = ((j < 2) ? bH0 : bH1) + (j & 1) * 2;
                const unsigned* bl = ((j < 2) ? bL0 : bL1) + (j & 1) * 2;
                mma16816(sacc[j], aH, bh);
                mma16816(sacc[j], aH, bl);
                mma16816(sacc[j], aL, bh);
            }
        }

        // ---- sigmoid + fp16 hi/lo split -> S[n][m] ----
        #pragma unroll
        for (int j = 0; j < 4; j++) {
            const int m   = m0w + j * 8 + (lane & 3) * 2;
            const int nb0 = n0q + (lane >> 2);
            #pragma unroll
            for (int h = 0; h < 2; h++) {
                const int n = nb0 + h * 8;
                float s0 = __fdividef(1.f, 1.f + __expf(-sacc[j][h * 2]));
                float s1 = __fdividef(1.f, 1.f + __expf(-sacc[j][h * 2 + 1]));
                __half h0 = __float2half_rn(s0), h1 = __float2half_rn(s1);
                __half l0 = __float2half_rn(s0 - __half2float(h0));
                __half l1 = __float2half_rn(s1 - __half2float(h1));
                *(half2*)(smh + SH_H + n * VSTR + m) = __halves2half2(h0, h1);
                *(half2*)(smh + SL_H + n * VSTR + m) = __halves2half2(l0, l1);
            }
        }
        cp_wait0();        // V ready
        __syncthreads();   // S visible to all warps

        // ---- PV: Fu[16c x 64n] per warp; Vh.Sh + Vh.Sl + Vl.Sh ----
        #pragma unroll
        for (int kk = 0; kk < 4; kk++) {
            const int mk = kk * 16;
            unsigned aVH[4], aVL[4];
            ldmA(aVH, base, VH_H, c0w, mk, VSTR, lane);
            ldmA(aVL, base, VL_H, c0w, mk, VSTR, lane);
            #pragma unroll
            for (int q = 0; q < 4; q++) {
                unsigned bSH[4], bSL[4];
                ldmB(bSH, base, SH_H, n0w + q * 16, mk, VSTR, lane);
                ldmB(bSL, base, SL_H, n0w + q * 16, mk, VSTR, lane);
                #pragma unroll
                for (int jj = 0; jj < 2; jj++) {
                    const int j = q * 2 + jj;
                    const unsigned* bh = bSH + jj * 2;
                    const unsigned* bl = bSL + jj * 2;
                    mma16816(facc[j], aVH, bh);
                    mma16816(facc[j], aVH, bl);
                    mma16816(facc[j], aVL, bh);
                }
            }
        }
    }

    // ---- epilogue: Fu -> channels [256,384) of y ----
    float* ob = out + (size_t)dir * NB * 384 * NPIX
                    + (size_t)b * 384 * NPIX + (size_t)256 * NPIX;
    #pragma unroll
    for (int j = 0; j < 8; j++) {
        const int n = n0w + j * 8 + (lane & 3) * 2;
        const int c = c0w + (lane >> 2);
        *(float2*)&ob[(size_t)c * NPIX + gn0 + n] =
            make_float2(facc[j][0], facc[j][1]);
        *(float2*)&ob[(size_t)(c + 8) * NPIX + gn0 + n] =
            make_float2(facc[j][2], facc[j][3]);
    }
}

// ---------------- launch ----------------
extern "C" void kernel_launch(void* const* d_in, const int* in_sizes, int n_in,
                              void* d_out, int out_size)
{
    const float* x1  = (const float*)d_in[0];
    const float* x2  = (const float*)d_in[1];
    const float* wv1 = (const float*)d_in[2];  const float* bv1 = (const float*)d_in[3];
    const float* wk1 = (const float*)d_in[4];  const float* bk1 = (const float*)d_in[5];
    const float* wq1 = (const float*)d_in[6];  const float* bq1 = (const float*)d_in[7];
    const float* wv2 = (const float*)d_in[8];  const float* bv2 = (const float*)d_in[9];
    const float* wk2 = (const float*)d_in[10]; const float* bk2 = (const float*)d_in[11];
    const float* wq2 = (const float*)d_in[12]; const float* bq2 = (const float*)d_in[13];
    float* out = (float*)d_out;

    wtrans_kernel<<<6, 256>>>(wv1, wk1, wq1, wv2, wk2, wq2);

    dim3 cg(NT, NB, 6);
    conv_kernel<<<cg, 256>>>(x1, x2, bv1, bk1, bq1, bv2, bk2, bq2);

    {
        size_t tot4 = 2ull * NB * CIN * NPIX / 4;
        int blocks = (int)((tot4 + 255) / 256);
        copyx_kernel<<<blocks, 256>>>(x1, x2, out);
    }

    size_t smem_bytes = (size_t)SMEM_HALVES * sizeof(__half);   // 194560 B
    cudaFuncSetAttribute(attn_kernel, cudaFuncAttributeMaxDynamicSharedMemorySize,
                         (int)smem_bytes);
    dim3 ag(NNT, NB, 2);
    attn_kernel<<<ag, 512, smem_bytes>>>(out);
}